// round 5
// baseline (speedup 1.0000x reference)
#include <cuda_runtime.h>
#include <cstdint>

#define NN 50000
#define EE 600000
#define IN_F 128
#define EF_F 64
#define HO 128

// ---------------- scratch (device globals; no allocations) ----------------
__device__ int   g_deg[NN];
__device__ int   g_rowptr[NN + 1];
__device__ int   g_csr_src[EE];
__device__ int   g_csr_eid[EE];
__device__ float g_feat[(size_t)NN * HO];
__device__ float g_res [(size_t)NN * HO];
__device__ float g_h   [(size_t)NN * HO];
__device__ float g_e   [(size_t)EE * HO];   // edge_fc output, stored in CSR order

// ---------------- CSR build ----------------
__global__ void __launch_bounds__(256) k_zero() {
    int i = blockIdx.x * 256 + threadIdx.x;
    if (i < NN) g_deg[i] = 0;
}

__global__ void __launch_bounds__(256) k_hist(const int* __restrict__ dst) {
    int i = blockIdx.x * 256 + threadIdx.x;
    if (i < EE) atomicAdd(&g_deg[dst[i]], 1);
}

// single-block exclusive scan over g_deg -> g_rowptr; also copies cursor into g_deg
__global__ void __launch_bounds__(1024) k_scan() {
    __shared__ int warpsums[32];
    __shared__ int s_carry;
    const int tid  = threadIdx.x;
    const int lane = tid & 31;
    const int wid  = tid >> 5;
    if (tid == 0) s_carry = 0;
    __syncthreads();
    for (int base = 0; base < NN; base += 1024) {
        int i = base + tid;
        int v = (i < NN) ? g_deg[i] : 0;
        int x = v;
        #pragma unroll
        for (int d = 1; d < 32; d <<= 1) {
            int y = __shfl_up_sync(0xffffffffu, x, d);
            if (lane >= d) x += y;
        }
        if (lane == 31) warpsums[wid] = x;
        __syncthreads();
        if (wid == 0) {
            int w = warpsums[lane];
            int xs = w;
            #pragma unroll
            for (int d = 1; d < 32; d <<= 1) {
                int y = __shfl_up_sync(0xffffffffu, xs, d);
                if (lane >= d) xs += y;
            }
            warpsums[lane] = xs - w;
        }
        __syncthreads();
        int carry = s_carry;
        int excl  = carry + warpsums[wid] + x - v;
        if (i < NN) { g_rowptr[i] = excl; g_deg[i] = excl; }
        __syncthreads();
        if (tid == 1023) s_carry = carry + warpsums[31] + x;
        __syncthreads();
    }
    if (tid == 0) g_rowptr[NN] = s_carry;
}

__global__ void __launch_bounds__(256) k_scatter(const int* __restrict__ src,
                                                 const int* __restrict__ dst) {
    int i = blockIdx.x * 256 + threadIdx.x;
    if (i < EE) {
        int d = dst[i];
        int p = atomicAdd(&g_deg[d], 1);
        g_csr_src[p] = src[i];
        g_csr_eid[p] = i;
    }
}

// ---------------- tf32 tensor-core GEMM ----------------
// C[r, 0:128] = A[row(r), 0:K] @ Wm[0:128, 0:K]^T + bias
// block tile 128x128, 8 warps (2 M x 4 N), warp tile 64x32, mma m16n8k8 tf32.
__device__ __forceinline__ uint32_t f2tf32(float f) {
    uint32_t u;
    asm("cvt.rna.tf32.f32 %0, %1;" : "=r"(u) : "f"(f));
    return u;
}

__device__ __forceinline__ void mma_tf32(float4& d, const uint32_t a[4], const uint32_t b[2]) {
    asm volatile(
        "mma.sync.aligned.m16n8k8.row.col.f32.tf32.tf32.f32 "
        "{%0,%1,%2,%3}, {%4,%5,%6,%7}, {%8,%9}, {%0,%1,%2,%3};"
        : "+f"(d.x), "+f"(d.y), "+f"(d.z), "+f"(d.w)
        : "r"(a[0]), "r"(a[1]), "r"(a[2]), "r"(a[3]), "r"(b[0]), "r"(b[1]));
}

#define AS_STRIDE 36   // 32 + 4 pad floats: bank = (4*row_off + tig) % 32, conflict-free

template <int K>
__global__ void __launch_bounds__(256) k_gemm_tc(const float* __restrict__ A, int nrows,
                                                 int use_gather,
                                                 const float* __restrict__ Wm,
                                                 const float* __restrict__ bias,
                                                 float* __restrict__ outp) {
    __shared__ uint32_t As[128 * AS_STRIDE];
    __shared__ uint32_t Bs[128 * AS_STRIDE];
    __shared__ int ridx[128];

    const int tid  = threadIdx.x;
    const int lane = tid & 31;
    const int wrp  = tid >> 5;
    const int wm   = wrp >> 2;        // 0..1 -> M offset wm*64
    const int wn   = wrp & 3;         // 0..3 -> N offset wn*32
    const int grp  = lane >> 2;       // 0..7
    const int tig  = lane & 3;        // 0..3
    const int rb   = blockIdx.x * 128;

    if (tid < 128) {
        int r = rb + tid;
        ridx[tid] = (r < nrows) ? (use_gather ? g_csr_eid[r] : r) : -1;
    }
    __syncthreads();

    float4 acc[4][4];
    #pragma unroll
    for (int i = 0; i < 4; i++)
        #pragma unroll
        for (int j = 0; j < 4; j++) acc[i][j] = make_float4(0.f, 0.f, 0.f, 0.f);

    for (int k0 = 0; k0 < K; k0 += 32) {
        // load A tile: 128 rows x 32 cols = 1024 float4
        #pragma unroll
        for (int t = 0; t < 4; t++) {
            int idx = tid + t * 256;
            int row = idx >> 3, q = idx & 7;
            float4 v = make_float4(0.f, 0.f, 0.f, 0.f);
            int gr = ridx[row];
            if (gr >= 0) v = *(const float4*)(A + (size_t)gr * K + k0 + q * 4);
            uint32_t* p = &As[row * AS_STRIDE + q * 4];
            p[0] = f2tf32(v.x); p[1] = f2tf32(v.y); p[2] = f2tf32(v.z); p[3] = f2tf32(v.w);
        }
        // load B tile: Bs[col][k] from Wm[col][k0+k]
        #pragma unroll
        for (int t = 0; t < 4; t++) {
            int idx = tid + t * 256;
            int col = idx >> 3, q = idx & 7;
            float4 v = *(const float4*)(Wm + (size_t)col * K + k0 + q * 4);
            uint32_t* p = &Bs[col * AS_STRIDE + q * 4];
            p[0] = f2tf32(v.x); p[1] = f2tf32(v.y); p[2] = f2tf32(v.z); p[3] = f2tf32(v.w);
        }
        __syncthreads();

        #pragma unroll
        for (int ks = 0; ks < 4; ks++) {
            const int kk = ks * 8;
            uint32_t bfr[4][2];
            #pragma unroll
            for (int nt = 0; nt < 4; nt++) {
                const uint32_t* bp = &Bs[(wn * 32 + nt * 8 + grp) * AS_STRIDE + kk + tig];
                bfr[nt][0] = bp[0];
                bfr[nt][1] = bp[4];
            }
            #pragma unroll
            for (int mt = 0; mt < 4; mt++) {
                uint32_t afr[4];
                const uint32_t* a0 = &As[(wm * 64 + mt * 16 + grp) * AS_STRIDE + kk + tig];
                const uint32_t* a1 = a0 + 8 * AS_STRIDE;
                afr[0] = a0[0]; afr[1] = a1[0]; afr[2] = a0[4]; afr[3] = a1[4];
                #pragma unroll
                for (int nt = 0; nt < 4; nt++)
                    mma_tf32(acc[mt][nt], afr, bfr[nt]);
            }
        }
        __syncthreads();
    }

    // epilogue: c0->(row, col), c1->(row, col+1), c2->(row+8, col), c3->(row+8, col+1)
    #pragma unroll
    for (int mt = 0; mt < 4; mt++) {
        int r0 = rb + wm * 64 + mt * 16 + grp;
        #pragma unroll
        for (int nt = 0; nt < 4; nt++) {
            int c = wn * 32 + nt * 8 + 2 * tig;
            float b0 = bias[c], b1 = bias[c + 1];
            if (r0 < nrows) {
                float2 o = make_float2(acc[mt][nt].x + b0, acc[mt][nt].y + b1);
                *(float2*)(outp + (size_t)r0 * HO + c) = o;
            }
            if (r0 + 8 < nrows) {
                float2 o = make_float2(acc[mt][nt].z + b0, acc[mt][nt].w + b1);
                *(float2*)(outp + (size_t)(r0 + 8) * HO + c) = o;
            }
        }
    }
}

// ---------------- stage 1: GATv2 attention + aggregate + residual + relu ----------------
__global__ void __launch_bounds__(256) k_gat(const float* __restrict__ attn_v) {
    int w = (blockIdx.x << 3) + (threadIdx.x >> 5);
    if (w >= NN) return;
    int lane = threadIdx.x & 31;
    int c = lane << 2;
    size_t nb = (size_t)w * HO + c;
    float4 fd = *(const float4*)(g_feat + nb);
    float4 av = *(const float4*)(attn_v + c);
    int beg = g_rowptr[w], end = g_rowptr[w + 1];
    float runM = -3.4e38f, runS = 0.f;
    float a0 = 0.f, a1 = 0.f, a2 = 0.f, a3 = 0.f;
    for (int i = beg; i < end; i++) {
        int s = g_csr_src[i];
        float4 fs = *(const float4*)(g_feat + (size_t)s * HO + c);
        float x0 = fs.x + fd.x, x1 = fs.y + fd.y, x2 = fs.z + fd.z, x3 = fs.w + fd.w;
        float e0 = fmaxf(x0, 0.f) + 0.2f * fminf(x0, 0.f);
        float e1 = fmaxf(x1, 0.f) + 0.2f * fminf(x1, 0.f);
        float e2 = fmaxf(x2, 0.f) + 0.2f * fminf(x2, 0.f);
        float e3 = fmaxf(x3, 0.f) + 0.2f * fminf(x3, 0.f);
        float sc = e0 * av.x + e1 * av.y + e2 * av.z + e3 * av.w;
        sc += __shfl_xor_sync(0xffffffffu, sc, 1);
        sc += __shfl_xor_sync(0xffffffffu, sc, 2);
        sc += __shfl_xor_sync(0xffffffffu, sc, 4);
        float nm  = fmaxf(runM, sc);
        float scl = __expf(runM - nm);
        float p   = __expf(sc - nm);
        runS = runS * scl + p;
        a0 = a0 * scl + p * fs.x;
        a1 = a1 * scl + p * fs.y;
        a2 = a2 * scl + p * fs.z;
        a3 = a3 * scl + p * fs.w;
        runM = nm;
    }
    float inv = (runS > 0.f) ? (1.f / runS) : 0.f;
    float4 rv = *(const float4*)(g_res + nb);
    float4 hv;
    hv.x = fmaxf(fmaf(a0, inv, rv.x), 0.f);
    hv.y = fmaxf(fmaf(a1, inv, rv.y), 0.f);
    hv.z = fmaxf(fmaf(a2, inv, rv.z), 0.f);
    hv.w = fmaxf(fmaf(a3, inv, rv.w), 0.f);
    *(float4*)(g_h + nb) = hv;
}

// ---------------- stage 2: m = h[src] + e ; componentwise segment softmax(m)*m ----------------
__global__ void __launch_bounds__(256) k_mail(float* __restrict__ out) {
    int w = (blockIdx.x << 3) + (threadIdx.x >> 5);
    if (w >= NN) return;
    int lane = threadIdx.x & 31;
    int c = lane << 2;
    int beg = g_rowptr[w], end = g_rowptr[w + 1];
    float M0 = -3.4e38f, M1 = -3.4e38f, M2 = -3.4e38f, M3 = -3.4e38f;
    float S0 = 0.f, S1 = 0.f, S2 = 0.f, S3 = 0.f;
    float Q0 = 0.f, Q1 = 0.f, Q2 = 0.f, Q3 = 0.f;
    for (int i = beg; i < end; i++) {
        int s = g_csr_src[i];
        float4 hv = *(const float4*)(g_h + (size_t)s * HO + c);
        float4 ev = *(const float4*)(g_e + (size_t)i * HO + c);
        float v0 = hv.x + ev.x, v1 = hv.y + ev.y, v2 = hv.z + ev.z, v3 = hv.w + ev.w;
        float nm0 = fmaxf(M0, v0), nm1 = fmaxf(M1, v1), nm2 = fmaxf(M2, v2), nm3 = fmaxf(M3, v3);
        float c0 = __expf(M0 - nm0), c1 = __expf(M1 - nm1), c2 = __expf(M2 - nm2), c3 = __expf(M3 - nm3);
        float p0 = __expf(v0 - nm0), p1 = __expf(v1 - nm1), p2 = __expf(v2 - nm2), p3 = __expf(v3 - nm3);
        S0 = S0 * c0 + p0; Q0 = Q0 * c0 + p0 * v0; M0 = nm0;
        S1 = S1 * c1 + p1; Q1 = Q1 * c1 + p1 * v1; M1 = nm1;
        S2 = S2 * c2 + p2; Q2 = Q2 * c2 + p2 * v2; M2 = nm2;
        S3 = S3 * c3 + p3; Q3 = Q3 * c3 + p3 * v3; M3 = nm3;
    }
    float4 o;
    o.x = (S0 > 0.f) ? (Q0 / S0) : 0.f;
    o.y = (S1 > 0.f) ? (Q1 / S1) : 0.f;
    o.z = (S2 > 0.f) ? (Q2 / S2) : 0.f;
    o.w = (S3 > 0.f) ? (Q3 / S3) : 0.f;
    *(float4*)(out + (size_t)w * HO + c) = o;
}

// ---------------- launch ----------------
extern "C" void kernel_launch(void* const* d_in, const int* in_sizes, int n_in,
                              void* d_out, int out_size) {
    const float* node_feats = (const float*)d_in[0];
    const float* edge_feats = (const float*)d_in[1];
    const int*   src        = (const int*)d_in[2];
    const int*   dst        = (const int*)d_in[3];
    const float* W          = (const float*)d_in[4];
    const float* b          = (const float*)d_in[5];
    const float* attn_v     = (const float*)d_in[6];
    const float* Wres       = (const float*)d_in[7];
    const float* bres       = (const float*)d_in[8];
    const float* We         = (const float*)d_in[9];
    const float* be         = (const float*)d_in[10];
    float* out = (float*)d_out;

    float* d_feat; cudaGetSymbolAddress((void**)&d_feat, g_feat);
    float* d_res;  cudaGetSymbolAddress((void**)&d_res,  g_res);
    float* d_e;    cudaGetSymbolAddress((void**)&d_e,    g_e);

    k_zero   <<<(NN + 255) / 256, 256>>>();
    k_hist   <<<(EE + 255) / 256, 256>>>(dst);
    k_scan   <<<1, 1024>>>();
    k_scatter<<<(EE + 255) / 256, 256>>>(src, dst);

    k_gemm_tc<128><<<(NN + 127) / 128, 256>>>(node_feats, NN, 0, W,    b,    d_feat);
    k_gemm_tc<128><<<(NN + 127) / 128, 256>>>(node_feats, NN, 0, Wres, bres, d_res);
    k_gemm_tc<64> <<<(EE + 127) / 128, 256>>>(edge_feats, EE, 1, We,   be,   d_e);

    k_gat <<<(NN + 7) / 8, 256>>>(attn_v);
    k_mail<<<(NN + 7) / 8, 256>>>(out);
}